// round 12
// baseline (speedup 1.0000x reference)
#include <cuda_runtime.h>
#include <cuda_bf16.h>
#include <math.h>
#include <stdint.h>

#define BB 8
#define CC 32
#define HH 256
#define WW 256
#define HW (HH*WW)

// ---------------- scratch (device globals; no allocations allowed) ----------
__device__ uint2 g_bufA2[(size_t)BB * 8 * HW];           // 32 MiB: conv out, pair layout
__device__ uint2 g_gated2[(size_t)BB * 8 * 4 * HW];      // 128 MiB: gated concat, pair layout
__device__ uint32_t g_wmapb[(size_t)BB * 4 * HW];        // 8 MiB: gate maps, dup'd bf16x2
__device__ uint4 g_wp[16384];                            // prepacked bf16 weights
__device__ __nv_bfloat16 g_att1[(size_t)BB * 16 * HW];   // 16 MiB: att1 planar

// g_wp offsets in uint4 units
#define WP_WIN 0
#define WP_W2  1296
#define WP_W3  6480
#define WP_AW1 11664
#define WP_AW2 12384

__device__ __forceinline__ uint32_t pbf(float lo, float hi) {
    uint32_t r;
    asm("cvt.rn.bf16x2.f32 %0, %1, %2;" : "=r"(r) : "f"(hi), "f"(lo));
    return r;
}
__device__ __forceinline__ uint32_t b2u(__nv_bfloat162 v) {
    return *reinterpret_cast<uint32_t*>(&v);
}
__device__ __forceinline__ __nv_bfloat162 u2b(uint32_t v) {
    return *reinterpret_cast<__nv_bfloat162*>(&v);
}

__device__ __forceinline__ void mma_bf16(float& d0, float& d1, float& d2, float& d3,
                                         uint32_t a0, uint32_t a1, uint32_t a2, uint32_t a3,
                                         uint32_t b0, uint32_t b1) {
    asm volatile(
        "mma.sync.aligned.m16n8k16.row.col.f32.bf16.bf16.f32 "
        "{%0,%1,%2,%3}, {%4,%5,%6,%7}, {%8,%9}, {%0,%1,%2,%3};"
        : "+f"(d0), "+f"(d1), "+f"(d2), "+f"(d3)
        : "r"(a0), "r"(a1), "r"(a2), "r"(a3), "r"(b0), "r"(b1));
}

// ---------------- setup: weight prepack only ---------------------------------
__global__ void setup_w(const float* __restrict__ w_in, const float* __restrict__ w2,
                        const float* __restrict__ w3, const float* __restrict__ aw1,
                        const float* __restrict__ aw2, uint2* __restrict__ wp2) {
    int i = blockIdx.x * 256 + threadIdx.x;
    if (i >= 25488) return;
    const float* src; int CIN, COUT, WP2, base; bool pairmap;
    if (i < 2592)       { src = w_in; CIN = 32;  COUT = 32; WP2 = 36; base = 0;     pairmap = false; }
    else if (i < 12960) { src = w2;   CIN = 128; COUT = 32; WP2 = 36; base = 2592;  pairmap = true; }
    else if (i < 23328) { src = w3;   CIN = 128; COUT = 32; WP2 = 36; base = 12960; pairmap = true; }
    else if (i < 24768) { src = aw1;  CIN = 32;  COUT = 16; WP2 = 20; base = 23328; pairmap = false; }
    else                { src = aw2;  CIN = 16;  COUT = 16; WP2 = 20; base = 24768; pairmap = false; }
    int j = i - base;
    int wpos = j % WP2; int rem = j / WP2;
    int t = rem & 3; rem >>= 2; int kk = rem % 9; int ch = rem / 9;
    uint2 v = make_uint2(0u, 0u);
    if (wpos < COUT) {
        if (!pairmap) {
            int cb = ch * 16 + 2 * t;
            v.x = pbf(src[((size_t)wpos * CIN + cb) * 9 + kk],     src[((size_t)wpos * CIN + cb + 1) * 9 + kk]);
            v.y = pbf(src[((size_t)wpos * CIN + cb + 8) * 9 + kk], src[((size_t)wpos * CIN + cb + 9) * 9 + kk]);
        } else {
            int d = ch >> 1, half = ch & 1;
            int c1 = d * 32 + half * 4 + t;
            v.x = pbf(src[((size_t)wpos * CIN + c1) * 9 + kk],      src[((size_t)wpos * CIN + c1 + 8) * 9 + kk]);
            v.y = pbf(src[((size_t)wpos * CIN + c1 + 16) * 9 + kk], src[((size_t)wpos * CIN + c1 + 24) * 9 + kk]);
        }
    }
    wp2[i] = v;
}

// ---------------- bf16 tensor-core 3x3 conv body -----------------------------
// F32IN: input is planar fp32 (x); staged synchronously with bf16 conversion.
// else: input is pair-layout uint2 (bf16), cp.async 3-stage pipeline.
template <int CIN, int COUT, bool RELU, int MODE, bool F32IN>
__device__ __forceinline__ void conv_body(const void* __restrict__ inp,
                                          const uint4* __restrict__ wpk,
                                          void* __restrict__ outp,
                                          const float* __restrict__ aux, int b) {
    constexpr int PLANE = 612;
    constexpr int WP2 = COUT + 4;
    constexpr int XBUF = 4 * PLANE;
    constexpr int WBUF = 9 * 4 * WP2;
    constexpr int NCH = CIN / 16;
    constexpr int NSL = 4 * 612;
    constexpr int WITER = (WBUF / 2 + 255) / 256;

    extern __shared__ uint2 sm[];
    uint2* s_x = sm;
    uint2* s_w = sm + 3 * XBUF;
    int* s_idx = (int*)(sm + 3 * (XBUF + WBUF));

    const int tid = threadIdx.x;
    const int lane = tid & 31, warp = tid >> 5;
    const int q = lane >> 2, t = lane & 3;
    const int w0 = blockIdx.x * 32, h0 = blockIdx.y * 16;

    for (int i = tid; i < NSL; i += 256) {
        int tt = i / 612, pos = i % 612;
        int y = pos / 34, xx = pos % 34;
        int gh = h0 + y - 1, gw = w0 + xx - 1;
        bool ok = (gh >= 0) && (gh < HH) && (gw >= 0) && (gw < WW);
        int ghc = min(max(gh, 0), HH - 1), gwc = min(max(gw, 0), WW - 1);
        int off8 = tt * HW + ghc * WW + gwc;
        s_idx[i] = off8 | ((ok ? 0 : 1) << 18);
    }

    const uint32_t smx = (uint32_t)__cvta_generic_to_shared(s_x);
    const uint32_t smw = (uint32_t)__cvta_generic_to_shared(s_w);

    auto stage_x = [&](int ch, int buf) {
        const char* base = (const char*)inp + ((size_t)b * NCH + ch) * 4 * HW * 8;
        uint32_t sb = smx + buf * (XBUF * 8);
#pragma unroll
        for (int j = 0; j < 10; j++) {
            int i = tid + j * 256;
            if (i < NSL) {
                int wv = s_idx[i];
                const char* src = base + ((size_t)(wv & 0x3FFFF)) * 8;
                int sz = ((wv >> 18) & 1) ? 0 : 8;
                asm volatile("cp.async.ca.shared.global [%0], [%1], 8, %2;"
                             :: "r"(sb + (unsigned)i * 8), "l"(src), "r"(sz));
            }
        }
    };
    auto stage_w = [&](int ch, int buf) {
        const uint4* src = wpk + ch * (WBUF / 2);
        uint32_t sb = smw + buf * (WBUF * 8);
#pragma unroll
        for (int j = 0; j < WITER; j++) {
            int i = tid + j * 256;
            if (i < WBUF / 2)
                asm volatile("cp.async.cg.shared.global [%0], [%1], 16;"
                             :: "r"(sb + (unsigned)i * 16), "l"(src + i));
        }
    };
    // F32IN sync staging: pair gather + bf16 pack from planar fp32
    auto stage_sync = [&](int ch, int buf) {
        const float* base = (const float*)inp + (size_t)b * CIN * HW + (size_t)ch * 16 * HW;
        uint2* dx = s_x + buf * XBUF;
#pragma unroll
        for (int j = 0; j < 10; j++) {
            int i = tid + j * 256;
            if (i < NSL) {
                int wv = s_idx[i];
                int tt = (wv >> 16) & 3;
                int pix = wv & 65535;
                bool bad = (wv >> 18) & 1;
                uint2 v = make_uint2(0u, 0u);
                if (!bad) {
                    const float* p = base + (size_t)(2 * tt) * HW + pix;
                    v.x = pbf(p[0], p[(size_t)HW]);
                    v.y = pbf(p[(size_t)8 * HW], p[(size_t)9 * HW]);
                }
                dx[i] = v;
            }
        }
        const uint4* srcw = wpk + ch * (WBUF / 2);
        uint4* dw = (uint4*)(s_w + buf * WBUF);
#pragma unroll
        for (int j = 0; j < WITER; j++) {
            int i = tid + j * 256;
            if (i < WBUF / 2) dw[i] = srcw[i];
        }
    };

    float acc0[8][4], acc1[8][4];
#pragma unroll
    for (int i = 0; i < 8; i++)
#pragma unroll
        for (int k = 0; k < 4; k++) { acc0[i][k] = 0.f; acc1[i][k] = 0.f; }

    if (!F32IN) {
        stage_x(0, 0); stage_w(0, 0);
        asm volatile("cp.async.commit_group;");
        if (NCH > 1) { stage_x(1, 1); stage_w(1, 1); }
        asm volatile("cp.async.commit_group;");
    }

#pragma unroll 1
    for (int c = 0; c < NCH; c++) {
        if (F32IN) {
            __syncthreads();
            stage_sync(c, c % 3);
            __syncthreads();
        } else {
            if (c + 1 < NCH) asm volatile("cp.async.wait_group 1;");
            else             asm volatile("cp.async.wait_group 0;");
            __syncthreads();
            if (c + 2 < NCH) {
                stage_x(c + 2, (c + 2) % 3); stage_w(c + 2, (c + 2) % 3);
                asm volatile("cp.async.commit_group;");
            }
        }

        const uint2* cx = s_x + (c % 3) * XBUF;
        const uint2* cw = s_w + (c % 3) * WBUF;
#pragma unroll
        for (int kk = 0; kk < 9; kk++) {
            const int ky = kk / 3, kx = kk % 3;
            const uint2* wb = cw + (kk * 4 + t) * WP2;
            uint2 w00 = wb[q], w01 = wb[q + 8];
            uint2 w10 = make_uint2(0, 0), w11 = make_uint2(0, 0);
            if (COUT == 32) { w10 = wb[q + 16]; w11 = wb[q + 24]; }
            const uint2* xb = cx + t * PLANE + ky * 34 + kx + q;
#pragma unroll
            for (int nt = 0; nt < 8; nt++) {
                int r = 2 * warp + (nt >> 2);
                int cb = (nt & 3) * 8;
                uint2 pb = xb[r * 34 + cb];
                mma_bf16(acc0[nt][0], acc0[nt][1], acc0[nt][2], acc0[nt][3],
                         w00.x, w01.x, w00.y, w01.y, pb.x, pb.y);
                if (COUT == 32)
                    mma_bf16(acc1[nt][0], acc1[nt][1], acc1[nt][2], acc1[nt][3],
                             w10.x, w11.x, w10.y, w11.y, pb.x, pb.y);
            }
        }
    }

    if (MODE == 1 && COUT == 32) {
        uint2* ob2 = (uint2*)outp + ((size_t)(b * 8 + q)) * HW;
#pragma unroll
        for (int nt = 0; nt < 8; nt++) {
            int h = h0 + 2 * warp + (nt >> 2);
            int w = w0 + (nt & 3) * 8 + 2 * t;
            size_t pix = (size_t)h * WW + w;
            float v00 = acc0[nt][0], v01 = acc0[nt][1];
            float v80 = acc0[nt][2], v81 = acc0[nt][3];
            float vG0 = acc1[nt][0], vG1 = acc1[nt][1];
            float vT0 = acc1[nt][2], vT1 = acc1[nt][3];
            if (RELU) {
                v00 = fmaxf(v00, 0.f); v01 = fmaxf(v01, 0.f);
                v80 = fmaxf(v80, 0.f); v81 = fmaxf(v81, 0.f);
                vG0 = fmaxf(vG0, 0.f); vG1 = fmaxf(vG1, 0.f);
                vT0 = fmaxf(vT0, 0.f); vT1 = fmaxf(vT1, 0.f);
            }
            uint4 st;
            st.x = pbf(v00, v80); st.y = pbf(vG0, vT0);
            st.z = pbf(v01, v81); st.w = pbf(vG1, vT1);
            *(uint4*)&ob2[pix] = st;
        }
    } else if (MODE == 1) {
        __nv_bfloat16* ob = (__nv_bfloat16*)outp + (size_t)b * COUT * HW;
#pragma unroll
        for (int nt = 0; nt < 8; nt++) {
            int h = h0 + 2 * warp + (nt >> 2);
            int w = w0 + (nt & 3) * 8 + 2 * t;
            size_t pix = (size_t)h * WW + w;
#pragma unroll
            for (int m = 0; m < 2; m++) {
                float v0 = acc0[nt][m * 2], v1 = acc0[nt][m * 2 + 1];
                if (RELU) { v0 = fmaxf(v0, 0.f); v1 = fmaxf(v1, 0.f); }
                int co = m * 8 + q;
                *(uint32_t*)&ob[(size_t)co * HW + pix] = pbf(v0, v1);
            }
        }
    } else {
        float wo0 = aux[q], wo1 = aux[q + 8], wo2 = aux[q + 16], wo3 = aux[q + 24];
        float* om = (float*)outp + (size_t)b * HW;
#pragma unroll
        for (int nt = 0; nt < 8; nt++) {
            int h = h0 + 2 * warp + (nt >> 2);
            int w = w0 + (nt & 3) * 8 + 2 * t;
            float v[8] = {acc0[nt][0], acc0[nt][1], acc0[nt][2], acc0[nt][3],
                          acc1[nt][0], acc1[nt][1], acc1[nt][2], acc1[nt][3]};
#pragma unroll
            for (int i = 0; i < 8; i++) v[i] = fmaxf(v[i], 0.f);
            float s0 = v[0] * wo0 + v[2] * wo1 + v[4] * wo2 + v[6] * wo3;
            float s1 = v[1] * wo0 + v[3] * wo1 + v[5] * wo2 + v[7] * wo3;
#pragma unroll
            for (int off = 4; off < 32; off <<= 1) {
                s0 += __shfl_xor_sync(0xffffffffu, s0, off);
                s1 += __shfl_xor_sync(0xffffffffu, s1, off);
            }
            if (q == 0) {
                float2 rr = make_float2(1.f / (1.f + expf(-s0)), 1.f / (1.f + expf(-s1)));
                *(float2*)&om[(size_t)h * WW + w] = rr;
            }
        }
    }
}

// ---------------- conv wrappers ----------------------------------------------
__global__ __launch_bounds__(256, 2)
void conv_stage1(const float* __restrict__ x, const uint4* __restrict__ wp,
                 uint2* __restrict__ bufA2, __nv_bfloat16* __restrict__ att1) {
    if (blockIdx.z < BB)
        conv_body<32, 32, false, 1, true>(x, wp + WP_WIN, bufA2, nullptr, blockIdx.z);
    else
        conv_body<32, 16, true, 1, true>(x, wp + WP_AW1, att1, nullptr, blockIdx.z - BB);
}
__global__ __launch_bounds__(256, 2)
void conv_mid(const uint2* __restrict__ g, const uint4* __restrict__ wp,
              uint2* __restrict__ bufA2) {
    conv_body<128, 32, false, 1, false>(g, wp + WP_W2, bufA2, nullptr, blockIdx.z);
}
__global__ __launch_bounds__(256, 2)
void conv_last(const uint2* __restrict__ g, const uint4* __restrict__ wp,
               float* __restrict__ out, const float* __restrict__ w_out) {
    conv_body<128, 32, true, 2, false>(g, wp + WP_W3, out, w_out, blockIdx.z);
}

// ---------------- att2 conv + fused 1x1->4 + sigmoid -> dup'd bf16 wmap ------
__global__ __launch_bounds__(256, 2)
void conv3x3_att2(const __nv_bfloat16* __restrict__ in, const uint4* __restrict__ wpk,
                  const float* __restrict__ w3, const float* __restrict__ b3,
                  uint32_t* __restrict__ wmapb) {
    constexpr int PLANE = 612;
    constexpr int WP2 = 20;
    __shared__ uint2 s_x[4 * PLANE];
    __shared__ uint2 s_w[9 * 4 * WP2];

    const int tid = threadIdx.x;
    const int lane = tid & 31, warp = tid >> 5;
    const int q = lane >> 2, t = lane & 3;
    const int w0 = blockIdx.x * 32, h0 = blockIdx.y * 16, b = blockIdx.z;

    const uint16_t* inb = (const uint16_t*)in + (size_t)b * 16 * HW;
    for (int i = tid; i < 4 * 612; i += 256) {
        int tt = i / 612, pos = i % 612;
        int y = pos / 34, xx = pos % 34;
        int gh = h0 + y - 1, gw = w0 + xx - 1;
        bool ok = (gh >= 0) && (gh < HH) && (gw >= 0) && (gw < WW);
        uint32_t wa = 0, wbv = 0;
        if (ok) {
            size_t o = (size_t)gh * WW + gw;
            uint32_t c0 = inb[(size_t)(2 * tt) * HW + o];
            uint32_t c1 = inb[(size_t)(2 * tt + 1) * HW + o];
            uint32_t c8 = inb[(size_t)(2 * tt + 8) * HW + o];
            uint32_t c9 = inb[(size_t)(2 * tt + 9) * HW + o];
            wa = c0 | (c1 << 16);
            wbv = c8 | (c9 << 16);
        }
        s_x[tt * PLANE + pos] = make_uint2(wa, wbv);
    }
    for (int i = tid; i < 9 * 4 * WP2 / 2; i += 256)
        ((uint4*)s_w)[i] = wpk[i];
    __syncthreads();

    float acc[8][4];
#pragma unroll
    for (int i = 0; i < 8; i++) { acc[i][0]=0.f; acc[i][1]=0.f; acc[i][2]=0.f; acc[i][3]=0.f; }

#pragma unroll
    for (int kk = 0; kk < 9; kk++) {
        const int ky = kk / 3, kx = kk % 3;
        const uint2* wb = s_w + (kk * 4 + t) * WP2;
        uint2 w00 = wb[q], w01 = wb[q + 8];
        const uint2* xb = s_x + t * PLANE + ky * 34 + kx + q;
#pragma unroll
        for (int nt = 0; nt < 8; nt++) {
            int r = 2 * warp + (nt >> 2);
            int cb = (nt & 3) * 8;
            uint2 pb = xb[r * 34 + cb];
            mma_bf16(acc[nt][0], acc[nt][1], acc[nt][2], acc[nt][3],
                     w00.x, w01.x, w00.y, w01.y, pb.x, pb.y);
        }
    }

    float w3a[4], w3b[4], b3v[4];
#pragma unroll
    for (int d = 0; d < 4; d++) {
        w3a[d] = w3[d * 16 + q];
        w3b[d] = w3[d * 16 + q + 8];
        b3v[d] = b3[d];
    }
    uint32_t* wm = wmapb + (size_t)b * 4 * HW;
#pragma unroll
    for (int nt = 0; nt < 8; nt++) {
        int h = h0 + 2 * warp + (nt >> 2);
        int w = w0 + (nt & 3) * 8 + 2 * t;
        float v0 = fmaxf(acc[nt][0], 0.f), v1 = fmaxf(acc[nt][1], 0.f);
        float v2 = fmaxf(acc[nt][2], 0.f), v3 = fmaxf(acc[nt][3], 0.f);
#pragma unroll
        for (int d = 0; d < 4; d++) {
            float s0 = v0 * w3a[d] + v2 * w3b[d];
            float s1 = v1 * w3a[d] + v3 * w3b[d];
#pragma unroll
            for (int off = 4; off < 32; off <<= 1) {
                s0 += __shfl_xor_sync(0xffffffffu, s0, off);
                s1 += __shfl_xor_sync(0xffffffffu, s1, off);
            }
            if (q == 0) {
                float m0 = 1.f / (1.f + expf(-(s0 + b3v[d])));
                float m1 = 1.f / (1.f + expf(-(s1 + b3v[d])));
                uint2 st = make_uint2(pbf(m0, m0), pbf(m1, m1));
                *(uint2*)&wm[(size_t)d * HW + (size_t)h * WW + w] = st;
            }
        }
    }
}

// ---------------- merged scans: z<8 vertical (32-row chunks), z>=8 horiz ----
#define HSTRIDE 261
__global__ __launch_bounds__(256, 4)
void scan_both(const uint2* __restrict__ bufA2, const float* __restrict__ alpha,
               const uint32_t* __restrict__ wmapb, uint2* __restrict__ gated2) {
    int b = blockIdx.x, q = blockIdx.y;
    float a0 = alpha[q], a1 = alpha[q + 8], a2 = alpha[q + 16], a3 = alpha[q + 24];
    __nv_bfloat16 h0b = __float2bfloat16_rn(a0), h1b = __float2bfloat16_rn(a1);
    __nv_bfloat16 h2b = __float2bfloat16_rn(a2), h3b = __float2bfloat16_rn(a3);
    __nv_bfloat162 ahi01 = __halves2bfloat162(h0b, h1b);
    __nv_bfloat162 ahi23 = __halves2bfloat162(h2b, h3b);
    __nv_bfloat162 alo01 = __halves2bfloat162(
        __float2bfloat16_rn(a0 - __bfloat162float(h0b)),
        __float2bfloat16_rn(a1 - __bfloat162float(h1b)));
    __nv_bfloat162 alo23 = __halves2bfloat162(
        __float2bfloat16_rn(a2 - __bfloat162float(h2b)),
        __float2bfloat16_rn(a3 - __bfloat162float(h3b)));
    const __nv_bfloat162 z2 = __float2bfloat162_rn(0.f);
    int half = q >> 2, tt = q & 3;

    if (blockIdx.z < 8) {
        // ------- vertical (dirs 0, 2), 32-row chunk, warm 16 -------
        int cn = blockIdx.z;
        int w = threadIdx.x;
        const uint2* xp = bufA2 + ((size_t)(b * 8 + q)) * HW + w;
        const uint32_t* wm0 = wmapb + ((size_t)b * 4 + 0) * HW + w;
        const uint32_t* wm2 = wmapb + ((size_t)b * 4 + 2) * HW + w;
        uint2* g0 = gated2 + ((size_t)((b * 8 + 0 + half) * 4 + tt)) * HW + w;
        uint2* g2 = gated2 + ((size_t)((b * 8 + 4 + half) * 4 + tt)) * HW + w;
        int h0 = cn * 32;

        __nv_bfloat162 p01 = z2, p23 = z2;
#pragma unroll 4
        for (int h = max(0, h0 - 16); h < h0 + 32; h++) {
            size_t o = (size_t)h * WW;
            uint2 wv = xp[o];
            __nv_bfloat162 v01 = __hfma2(ahi01, p01, u2b(wv.x));
            v01 = __hfma2(alo01, p01, v01);
            v01 = __hmax2(v01, z2);
            __nv_bfloat162 v23 = __hfma2(ahi23, p23, u2b(wv.y));
            v23 = __hfma2(alo23, p23, v23);
            v23 = __hmax2(v23, z2);
            if (h >= h0) {
                __nv_bfloat162 m2 = u2b(wm0[o]);
                g0[o] = make_uint2(b2u(__hmul2(v01, m2)), b2u(__hmul2(v23, m2)));
            }
            p01 = v01; p23 = v23;
        }
        p01 = z2; p23 = z2;
#pragma unroll 4
        for (int h = min(HH - 1, h0 + 31 + 16); h >= h0; h--) {
            size_t o = (size_t)h * WW;
            uint2 wv = xp[o];
            __nv_bfloat162 v01 = __hfma2(ahi01, p01, u2b(wv.x));
            v01 = __hfma2(alo01, p01, v01);
            v01 = __hmax2(v01, z2);
            __nv_bfloat162 v23 = __hfma2(ahi23, p23, u2b(wv.y));
            v23 = __hfma2(alo23, p23, v23);
            v23 = __hmax2(v23, z2);
            if (h < h0 + 32) {
                __nv_bfloat162 m2 = u2b(wm2[o]);
                g2[o] = make_uint2(b2u(__hmul2(v01, m2)), b2u(__hmul2(v23, m2)));
            }
            p01 = v01; p23 = v23;
        }
        return;
    }

    // ------- horizontal (dirs 1, 3), 8-row block, 16-col chunks, warm 16 -------
    extern __shared__ uint2 shu[];
    uint2* tin = shu;
    uint2* tf  = shu + 8 * HSTRIDE;
    uint2* tr  = shu + 16 * HSTRIDE;

    int rb = blockIdx.z - 8;
    int R0 = rb * 8;
    const int tid = threadIdx.x;

    const uint2* xp = bufA2 + ((size_t)(b * 8 + q)) * HW + (size_t)R0 * WW;
    for (int i = tid; i < 8 * 256; i += 256) {
        int r = i >> 8, col = i & 255;
        tin[r * HSTRIDE + col] = xp[(size_t)r * WW + col];
    }
    __syncthreads();

    {
        int dir = tid >> 7, rem = tid & 127;
        int r = rem & 7, ck = rem >> 3;
        int base = ck * 16;
        uint2* dst = dir ? tr : tf;
        __nv_bfloat162 p01 = z2, p23 = z2;
        if (!dir) {
            for (int col = max(0, base - 16); col < base + 16; col++) {
                uint2 wv = tin[r * HSTRIDE + col];
                __nv_bfloat162 v01 = __hfma2(ahi01, p01, u2b(wv.x));
                v01 = __hfma2(alo01, p01, v01);
                v01 = __hmax2(v01, z2);
                __nv_bfloat162 v23 = __hfma2(ahi23, p23, u2b(wv.y));
                v23 = __hfma2(alo23, p23, v23);
                v23 = __hmax2(v23, z2);
                if (col >= base)
                    dst[r * HSTRIDE + col] = make_uint2(b2u(v01), b2u(v23));
                p01 = v01; p23 = v23;
            }
        } else {
            for (int col = min(255, base + 31); col >= base; col--) {
                uint2 wv = tin[r * HSTRIDE + col];
                __nv_bfloat162 v01 = __hfma2(ahi01, p01, u2b(wv.x));
                v01 = __hfma2(alo01, p01, v01);
                v01 = __hmax2(v01, z2);
                __nv_bfloat162 v23 = __hfma2(ahi23, p23, u2b(wv.y));
                v23 = __hfma2(alo23, p23, v23);
                v23 = __hmax2(v23, z2);
                if (col < base + 16)
                    dst[r * HSTRIDE + col] = make_uint2(b2u(v01), b2u(v23));
                p01 = v01; p23 = v23;
            }
        }
    }
    __syncthreads();

    const uint32_t* wm1 = wmapb + ((size_t)b * 4 + 1) * HW + (size_t)R0 * WW;
    const uint32_t* wm3 = wmapb + ((size_t)b * 4 + 3) * HW + (size_t)R0 * WW;
    uint2* g1 = gated2 + ((size_t)((b * 8 + 2 + half) * 4 + tt)) * HW + (size_t)R0 * WW;
    uint2* g3 = gated2 + ((size_t)((b * 8 + 6 + half) * 4 + tt)) * HW + (size_t)R0 * WW;
    for (int i = tid; i < 8 * 256; i += 256) {
        int r = i >> 8, col = i & 255;
        __nv_bfloat162 m1 = u2b(wm1[i]);
        __nv_bfloat162 m3 = u2b(wm3[i]);
        uint2 f = tf[r * HSTRIDE + col];
        uint2 rv = tr[r * HSTRIDE + col];
        g1[i] = make_uint2(b2u(__hmul2(u2b(f.x), m1)), b2u(__hmul2(u2b(f.y), m1)));
        g3[i] = make_uint2(b2u(__hmul2(u2b(rv.x), m3)), b2u(__hmul2(u2b(rv.y), m3)));
    }
}

// ---------------- launch ------------------------------------------------------
extern "C" void kernel_launch(void* const* d_in, const int* in_sizes, int n_in,
                              void* d_out, int out_size) {
    const float* x      = (const float*)d_in[0];
    const float* alpha1 = (const float*)d_in[1];
    const float* alpha2 = (const float*)d_in[2];
    const float* w_in   = (const float*)d_in[3];
    const float* w2     = (const float*)d_in[4];
    const float* w3     = (const float*)d_in[5];
    const float* att_w1 = (const float*)d_in[6];
    const float* att_w2 = (const float*)d_in[7];
    const float* att_w3 = (const float*)d_in[8];
    const float* att_b3 = (const float*)d_in[9];
    const float* w_out  = (const float*)d_in[10];
    float* out = (float*)d_out;

    __nv_bfloat16 *att1;
    uint32_t *wmapb;
    uint2 *bufA2, *gated2;
    uint4* wp;
    cudaGetSymbolAddress((void**)&bufA2, g_bufA2);
    cudaGetSymbolAddress((void**)&gated2, g_gated2);
    cudaGetSymbolAddress((void**)&wmapb, g_wmapb);
    cudaGetSymbolAddress((void**)&wp, g_wp);
    cudaGetSymbolAddress((void**)&att1, g_att1);

    constexpr int SMP32 = 3 * (2448 + 9 * 4 * 36) * 8 + 2448 * 4;   // 99648
    constexpr int SMH   = 24 * HSTRIDE * 8;                          // 50112
    cudaFuncSetAttribute(conv_stage1, cudaFuncAttributeMaxDynamicSharedMemorySize, SMP32);
    cudaFuncSetAttribute(conv_mid, cudaFuncAttributeMaxDynamicSharedMemorySize, SMP32);
    cudaFuncSetAttribute(conv_last, cudaFuncAttributeMaxDynamicSharedMemorySize, SMP32);
    cudaFuncSetAttribute(scan_both, cudaFuncAttributeMaxDynamicSharedMemorySize, SMH);

    dim3 blk(256);
    // 1) setup: prepack weights only (x read directly by stage1)
    setup_w<<<100, blk>>>(w_in, w2, w3, att_w1, att_w2, (uint2*)wp);

    // 2) conv1 (trunk) + att1 (attention), reading fp32 x directly
    conv_stage1<<<dim3(WW / 32, HH / 16, 2 * BB), blk, SMP32>>>(x, wp, bufA2, att1);

    // 3) att2 + fused 1x1 + sigmoid -> wmapb (dup'd bf16)
    conv3x3_att2<<<dim3(WW / 32, HH / 16, BB), blk>>>(att1, wp + WP_AW2, att_w3, att_b3, wmapb);

    // 4) scans stage 1
    scan_both<<<dim3(BB, 8, 40), blk, SMH>>>(bufA2, alpha1, wmapb, gated2);

    // 5) conv2
    conv_mid<<<dim3(WW / 32, HH / 16, BB), blk, SMP32>>>(gated2, wp, bufA2);

    // 6) scans stage 2
    scan_both<<<dim3(BB, 8, 40), blk, SMH>>>(bufA2, alpha2, wmapb, gated2);

    // 7) conv3 + fused 1x1 + sigmoid -> mask
    conv_last<<<dim3(WW / 32, HH / 16, BB), blk, SMP32>>>(gated2, wp, out, w_out);
}

// round 13
// speedup vs baseline: 1.1091x; 1.1091x over previous
#include <cuda_runtime.h>
#include <cuda_bf16.h>
#include <math.h>
#include <stdint.h>

#define BB 8
#define CC 32
#define HH 256
#define WW 256
#define HW (HH*WW)

// ---------------- scratch (device globals; no allocations allowed) ----------
__device__ uint2 g_bufA2[(size_t)BB * 8 * HW];           // 32 MiB: conv out, pair layout
__device__ uint2 g_gated2[(size_t)BB * 8 * 4 * HW];      // 128 MiB: gated concat, pair layout
__device__ uint32_t g_wmapb[(size_t)BB * 4 * HW];        // 8 MiB: gate maps, dup'd bf16x2
__device__ uint2 g_x2[(size_t)BB * 2 * 4 * HW];          // 32 MiB: bf16-packed x
__device__ uint4 g_wp[16384];                            // prepacked bf16 weights
__device__ __nv_bfloat16 g_att1[(size_t)BB * 16 * HW];   // 16 MiB: att1 planar

// g_wp offsets in uint4 units
#define WP_WIN 0
#define WP_W2  1296
#define WP_W3  6480
#define WP_AW1 11664
#define WP_AW2 12384

__device__ __forceinline__ uint32_t pbf(float lo, float hi) {
    uint32_t r;
    asm("cvt.rn.bf16x2.f32 %0, %1, %2;" : "=r"(r) : "f"(hi), "f"(lo));
    return r;
}
__device__ __forceinline__ uint32_t b2u(__nv_bfloat162 v) {
    return *reinterpret_cast<uint32_t*>(&v);
}
__device__ __forceinline__ __nv_bfloat162 u2b(uint32_t v) {
    return *reinterpret_cast<__nv_bfloat162*>(&v);
}

__device__ __forceinline__ void mma_bf16(float& d0, float& d1, float& d2, float& d3,
                                         uint32_t a0, uint32_t a1, uint32_t a2, uint32_t a3,
                                         uint32_t b0, uint32_t b1) {
    asm volatile(
        "mma.sync.aligned.m16n8k16.row.col.f32.bf16.bf16.f32 "
        "{%0,%1,%2,%3}, {%4,%5,%6,%7}, {%8,%9}, {%0,%1,%2,%3};"
        : "+f"(d0), "+f"(d1), "+f"(d2), "+f"(d3)
        : "r"(a0), "r"(a1), "r"(a2), "r"(a3), "r"(b0), "r"(b1));
}

// ---------------- merged setup: repack_x + all weight prepacks ---------------
#define NXB 16384
__global__ void setup_all(const float* __restrict__ x, uint2* __restrict__ x2,
                          const float* __restrict__ w_in, const float* __restrict__ w2,
                          const float* __restrict__ w3, const float* __restrict__ aw1,
                          const float* __restrict__ aw2, uint2* __restrict__ wp2) {
    if (blockIdx.x < NXB) {
        size_t i = (size_t)blockIdx.x * 256 + threadIdx.x;
        int p = (int)(i & (HW - 1));
        int pl = (int)(i >> 16);
        int b = pl >> 3, ch = (pl >> 2) & 1, t = pl & 3;
        const float* s = x + ((size_t)(b * CC + ch * 16 + 2 * t)) * HW + p;
        uint2 v;
        v.x = pbf(s[0], s[(size_t)HW]);
        v.y = pbf(s[(size_t)8 * HW], s[(size_t)9 * HW]);
        x2[i] = v;
        return;
    }
    int i = (blockIdx.x - NXB) * 256 + threadIdx.x;
    if (i >= 25488) return;
    const float* src; int CIN, COUT, WP2, base; bool pairmap;
    if (i < 2592)       { src = w_in; CIN = 32;  COUT = 32; WP2 = 36; base = 0;     pairmap = false; }
    else if (i < 12960) { src = w2;   CIN = 128; COUT = 32; WP2 = 36; base = 2592;  pairmap = true; }
    else if (i < 23328) { src = w3;   CIN = 128; COUT = 32; WP2 = 36; base = 12960; pairmap = true; }
    else if (i < 24768) { src = aw1;  CIN = 32;  COUT = 16; WP2 = 20; base = 23328; pairmap = false; }
    else                { src = aw2;  CIN = 16;  COUT = 16; WP2 = 20; base = 24768; pairmap = false; }
    int j = i - base;
    int wpos = j % WP2; int rem = j / WP2;
    int t = rem & 3; rem >>= 2; int kk = rem % 9; int ch = rem / 9;
    uint2 v = make_uint2(0u, 0u);
    if (wpos < COUT) {
        if (!pairmap) {
            int cb = ch * 16 + 2 * t;
            v.x = pbf(src[((size_t)wpos * CIN + cb) * 9 + kk],     src[((size_t)wpos * CIN + cb + 1) * 9 + kk]);
            v.y = pbf(src[((size_t)wpos * CIN + cb + 8) * 9 + kk], src[((size_t)wpos * CIN + cb + 9) * 9 + kk]);
        } else {
            int d = ch >> 1, half = ch & 1;
            int c1 = d * 32 + half * 4 + t;
            v.x = pbf(src[((size_t)wpos * CIN + c1) * 9 + kk],      src[((size_t)wpos * CIN + c1 + 8) * 9 + kk]);
            v.y = pbf(src[((size_t)wpos * CIN + c1 + 16) * 9 + kk], src[((size_t)wpos * CIN + c1 + 24) * 9 + kk]);
        }
    }
    wp2[i] = v;
}

// ---------------- bf16 tensor-core 3x3 conv body (pair-layout input) ---------
template <int CIN, int COUT, bool RELU, int MODE>
__device__ __forceinline__ void conv_body(const uint2* __restrict__ in2,
                                          const uint4* __restrict__ wpk,
                                          void* __restrict__ outp,
                                          const float* __restrict__ aux, int b) {
    constexpr int PLANE = 612;
    constexpr int WP2 = COUT + 4;
    constexpr int XBUF = 4 * PLANE;
    constexpr int WBUF = 9 * 4 * WP2;
    constexpr int NCH = CIN / 16;
    constexpr int NSL = 4 * 612;
    constexpr int WITER = (WBUF / 2 + 255) / 256;

    extern __shared__ uint2 sm[];
    uint2* s_x = sm;
    uint2* s_w = sm + 3 * XBUF;
    int* s_idx = (int*)(sm + 3 * (XBUF + WBUF));

    const int tid = threadIdx.x;
    const int lane = tid & 31, warp = tid >> 5;
    const int q = lane >> 2, t = lane & 3;
    const int w0 = blockIdx.x * 32, h0 = blockIdx.y * 16;

    for (int i = tid; i < NSL; i += 256) {
        int tt = i / 612, pos = i % 612;
        int y = pos / 34, xx = pos % 34;
        int gh = h0 + y - 1, gw = w0 + xx - 1;
        bool ok = (gh >= 0) && (gh < HH) && (gw >= 0) && (gw < WW);
        int ghc = min(max(gh, 0), HH - 1), gwc = min(max(gw, 0), WW - 1);
        int off8 = tt * HW + ghc * WW + gwc;
        s_idx[i] = off8 | ((ok ? 0 : 1) << 18);
    }

    const uint32_t smx = (uint32_t)__cvta_generic_to_shared(s_x);
    const uint32_t smw = (uint32_t)__cvta_generic_to_shared(s_w);

    auto stage_x = [&](int ch, int buf) {
        const char* base = (const char*)in2 + ((size_t)b * NCH + ch) * 4 * HW * 8;
        uint32_t sb = smx + buf * (XBUF * 8);
#pragma unroll
        for (int j = 0; j < 10; j++) {
            int i = tid + j * 256;
            if (i < NSL) {
                int wv = s_idx[i];
                const char* src = base + ((size_t)(wv & 0x3FFFF)) * 8;
                int sz = ((wv >> 18) & 1) ? 0 : 8;
                asm volatile("cp.async.ca.shared.global [%0], [%1], 8, %2;"
                             :: "r"(sb + (unsigned)i * 8), "l"(src), "r"(sz));
            }
        }
    };
    auto stage_w = [&](int ch, int buf) {
        const uint4* src = wpk + ch * (WBUF / 2);
        uint32_t sb = smw + buf * (WBUF * 8);
#pragma unroll
        for (int j = 0; j < WITER; j++) {
            int i = tid + j * 256;
            if (i < WBUF / 2)
                asm volatile("cp.async.cg.shared.global [%0], [%1], 16;"
                             :: "r"(sb + (unsigned)i * 16), "l"(src + i));
        }
    };

    float acc0[8][4], acc1[8][4];
#pragma unroll
    for (int i = 0; i < 8; i++)
#pragma unroll
        for (int k = 0; k < 4; k++) { acc0[i][k] = 0.f; acc1[i][k] = 0.f; }

    stage_x(0, 0); stage_w(0, 0);
    asm volatile("cp.async.commit_group;");
    if (NCH > 1) { stage_x(1, 1); stage_w(1, 1); }
    asm volatile("cp.async.commit_group;");

#pragma unroll 1
    for (int c = 0; c < NCH; c++) {
        if (c + 1 < NCH) asm volatile("cp.async.wait_group 1;");
        else             asm volatile("cp.async.wait_group 0;");
        __syncthreads();
        if (c + 2 < NCH) {
            stage_x(c + 2, (c + 2) % 3); stage_w(c + 2, (c + 2) % 3);
            asm volatile("cp.async.commit_group;");
        }

        const uint2* cx = s_x + (c % 3) * XBUF;
        const uint2* cw = s_w + (c % 3) * WBUF;
#pragma unroll
        for (int kk = 0; kk < 9; kk++) {
            const int ky = kk / 3, kx = kk % 3;
            const uint2* wb = cw + (kk * 4 + t) * WP2;
            uint2 w00 = wb[q], w01 = wb[q + 8];
            uint2 w10 = make_uint2(0, 0), w11 = make_uint2(0, 0);
            if (COUT == 32) { w10 = wb[q + 16]; w11 = wb[q + 24]; }
            const uint2* xb = cx + t * PLANE + ky * 34 + kx + q;
#pragma unroll
            for (int nt = 0; nt < 8; nt++) {
                int r = 2 * warp + (nt >> 2);
                int cb = (nt & 3) * 8;
                uint2 pb = xb[r * 34 + cb];
                mma_bf16(acc0[nt][0], acc0[nt][1], acc0[nt][2], acc0[nt][3],
                         w00.x, w01.x, w00.y, w01.y, pb.x, pb.y);
                if (COUT == 32)
                    mma_bf16(acc1[nt][0], acc1[nt][1], acc1[nt][2], acc1[nt][3],
                             w10.x, w11.x, w10.y, w11.y, pb.x, pb.y);
            }
        }
    }

    if (MODE == 1 && COUT == 32) {
        uint2* ob2 = (uint2*)outp + ((size_t)(b * 8 + q)) * HW;
#pragma unroll
        for (int nt = 0; nt < 8; nt++) {
            int h = h0 + 2 * warp + (nt >> 2);
            int w = w0 + (nt & 3) * 8 + 2 * t;
            size_t pix = (size_t)h * WW + w;
            float v00 = acc0[nt][0], v01 = acc0[nt][1];
            float v80 = acc0[nt][2], v81 = acc0[nt][3];
            float vG0 = acc1[nt][0], vG1 = acc1[nt][1];
            float vT0 = acc1[nt][2], vT1 = acc1[nt][3];
            if (RELU) {
                v00 = fmaxf(v00, 0.f); v01 = fmaxf(v01, 0.f);
                v80 = fmaxf(v80, 0.f); v81 = fmaxf(v81, 0.f);
                vG0 = fmaxf(vG0, 0.f); vG1 = fmaxf(vG1, 0.f);
                vT0 = fmaxf(vT0, 0.f); vT1 = fmaxf(vT1, 0.f);
            }
            uint4 st;
            st.x = pbf(v00, v80); st.y = pbf(vG0, vT0);
            st.z = pbf(v01, v81); st.w = pbf(vG1, vT1);
            *(uint4*)&ob2[pix] = st;
        }
    } else if (MODE == 1) {
        __nv_bfloat16* ob = (__nv_bfloat16*)outp + (size_t)b * COUT * HW;
#pragma unroll
        for (int nt = 0; nt < 8; nt++) {
            int h = h0 + 2 * warp + (nt >> 2);
            int w = w0 + (nt & 3) * 8 + 2 * t;
            size_t pix = (size_t)h * WW + w;
#pragma unroll
            for (int m = 0; m < 2; m++) {
                float v0 = acc0[nt][m * 2], v1 = acc0[nt][m * 2 + 1];
                if (RELU) { v0 = fmaxf(v0, 0.f); v1 = fmaxf(v1, 0.f); }
                int co = m * 8 + q;
                *(uint32_t*)&ob[(size_t)co * HW + pix] = pbf(v0, v1);
            }
        }
    } else {
        float wo0 = aux[q], wo1 = aux[q + 8], wo2 = aux[q + 16], wo3 = aux[q + 24];
        float* om = (float*)outp + (size_t)b * HW;
#pragma unroll
        for (int nt = 0; nt < 8; nt++) {
            int h = h0 + 2 * warp + (nt >> 2);
            int w = w0 + (nt & 3) * 8 + 2 * t;
            float v[8] = {acc0[nt][0], acc0[nt][1], acc0[nt][2], acc0[nt][3],
                          acc1[nt][0], acc1[nt][1], acc1[nt][2], acc1[nt][3]};
#pragma unroll
            for (int i = 0; i < 8; i++) v[i] = fmaxf(v[i], 0.f);
            float s0 = v[0] * wo0 + v[2] * wo1 + v[4] * wo2 + v[6] * wo3;
            float s1 = v[1] * wo0 + v[3] * wo1 + v[5] * wo2 + v[7] * wo3;
#pragma unroll
            for (int off = 4; off < 32; off <<= 1) {
                s0 += __shfl_xor_sync(0xffffffffu, s0, off);
                s1 += __shfl_xor_sync(0xffffffffu, s1, off);
            }
            if (q == 0) {
                float2 rr = make_float2(1.f / (1.f + expf(-s0)), 1.f / (1.f + expf(-s1)));
                *(float2*)&om[(size_t)h * WW + w] = rr;
            }
        }
    }
}

// ---------------- conv wrappers ----------------------------------------------
__global__ __launch_bounds__(256, 2)
void conv_stage1(const uint2* __restrict__ x2, const uint4* __restrict__ wp,
                 uint2* __restrict__ bufA2, __nv_bfloat16* __restrict__ att1) {
    if (blockIdx.z < BB)
        conv_body<32, 32, false, 1>(x2, wp + WP_WIN, bufA2, nullptr, blockIdx.z);
    else
        conv_body<32, 16, true, 1>(x2, wp + WP_AW1, att1, nullptr, blockIdx.z - BB);
}
__global__ __launch_bounds__(256, 2)
void conv_mid(const uint2* __restrict__ g, const uint4* __restrict__ wp,
              uint2* __restrict__ bufA2) {
    conv_body<128, 32, false, 1>(g, wp + WP_W2, bufA2, nullptr, blockIdx.z);
}
__global__ __launch_bounds__(256, 2)
void conv_last(const uint2* __restrict__ g, const uint4* __restrict__ wp,
               float* __restrict__ out, const float* __restrict__ w_out) {
    conv_body<128, 32, true, 2>(g, wp + WP_W3, out, w_out, blockIdx.z);
}

// ---------------- att2 conv + fused 1x1->4 + sigmoid -> dup'd bf16 wmap ------
__global__ __launch_bounds__(256, 2)
void conv3x3_att2(const __nv_bfloat16* __restrict__ in, const uint4* __restrict__ wpk,
                  const float* __restrict__ w3, const float* __restrict__ b3,
                  uint32_t* __restrict__ wmapb) {
    constexpr int PLANE = 612;
    constexpr int WP2 = 20;
    __shared__ uint2 s_x[4 * PLANE];
    __shared__ uint2 s_w[9 * 4 * WP2];

    const int tid = threadIdx.x;
    const int lane = tid & 31, warp = tid >> 5;
    const int q = lane >> 2, t = lane & 3;
    const int w0 = blockIdx.x * 32, h0 = blockIdx.y * 16, b = blockIdx.z;

    const uint16_t* inb = (const uint16_t*)in + (size_t)b * 16 * HW;
    for (int i = tid; i < 4 * 612; i += 256) {
        int tt = i / 612, pos = i % 612;
        int y = pos / 34, xx = pos % 34;
        int gh = h0 + y - 1, gw = w0 + xx - 1;
        bool ok = (gh >= 0) && (gh < HH) && (gw >= 0) && (gw < WW);
        uint32_t wa = 0, wbv = 0;
        if (ok) {
            size_t o = (size_t)gh * WW + gw;
            uint32_t c0 = inb[(size_t)(2 * tt) * HW + o];
            uint32_t c1 = inb[(size_t)(2 * tt + 1) * HW + o];
            uint32_t c8 = inb[(size_t)(2 * tt + 8) * HW + o];
            uint32_t c9 = inb[(size_t)(2 * tt + 9) * HW + o];
            wa = c0 | (c1 << 16);
            wbv = c8 | (c9 << 16);
        }
        s_x[tt * PLANE + pos] = make_uint2(wa, wbv);
    }
    for (int i = tid; i < 9 * 4 * WP2 / 2; i += 256)
        ((uint4*)s_w)[i] = wpk[i];
    __syncthreads();

    float acc[8][4];
#pragma unroll
    for (int i = 0; i < 8; i++) { acc[i][0]=0.f; acc[i][1]=0.f; acc[i][2]=0.f; acc[i][3]=0.f; }

#pragma unroll
    for (int kk = 0; kk < 9; kk++) {
        const int ky = kk / 3, kx = kk % 3;
        const uint2* wb = s_w + (kk * 4 + t) * WP2;
        uint2 w00 = wb[q], w01 = wb[q + 8];
        const uint2* xb = s_x + t * PLANE + ky * 34 + kx + q;
#pragma unroll
        for (int nt = 0; nt < 8; nt++) {
            int r = 2 * warp + (nt >> 2);
            int cb = (nt & 3) * 8;
            uint2 pb = xb[r * 34 + cb];
            mma_bf16(acc[nt][0], acc[nt][1], acc[nt][2], acc[nt][3],
                     w00.x, w01.x, w00.y, w01.y, pb.x, pb.y);
        }
    }

    float w3a[4], w3b[4], b3v[4];
#pragma unroll
    for (int d = 0; d < 4; d++) {
        w3a[d] = w3[d * 16 + q];
        w3b[d] = w3[d * 16 + q + 8];
        b3v[d] = b3[d];
    }
    uint32_t* wm = wmapb + (size_t)b * 4 * HW;
#pragma unroll
    for (int nt = 0; nt < 8; nt++) {
        int h = h0 + 2 * warp + (nt >> 2);
        int w = w0 + (nt & 3) * 8 + 2 * t;
        float v0 = fmaxf(acc[nt][0], 0.f), v1 = fmaxf(acc[nt][1], 0.f);
        float v2 = fmaxf(acc[nt][2], 0.f), v3 = fmaxf(acc[nt][3], 0.f);
#pragma unroll
        for (int d = 0; d < 4; d++) {
            float s0 = v0 * w3a[d] + v2 * w3b[d];
            float s1 = v1 * w3a[d] + v3 * w3b[d];
#pragma unroll
            for (int off = 4; off < 32; off <<= 1) {
                s0 += __shfl_xor_sync(0xffffffffu, s0, off);
                s1 += __shfl_xor_sync(0xffffffffu, s1, off);
            }
            if (q == 0) {
                float m0 = 1.f / (1.f + expf(-(s0 + b3v[d])));
                float m1 = 1.f / (1.f + expf(-(s1 + b3v[d])));
                uint2 st = make_uint2(pbf(m0, m0), pbf(m1, m1));
                *(uint2*)&wm[(size_t)d * HW + (size_t)h * WW + w] = st;
            }
        }
    }
}

// ---------------- merged scans: z<8 vertical (32-row chunks), z>=8 horiz ----
#define HSTRIDE 261
__global__ __launch_bounds__(256, 4)
void scan_both(const uint2* __restrict__ bufA2, const float* __restrict__ alpha,
               const uint32_t* __restrict__ wmapb, uint2* __restrict__ gated2) {
    int b = blockIdx.x, q = blockIdx.y;
    float a0 = alpha[q], a1 = alpha[q + 8], a2 = alpha[q + 16], a3 = alpha[q + 24];
    __nv_bfloat16 h0b = __float2bfloat16_rn(a0), h1b = __float2bfloat16_rn(a1);
    __nv_bfloat16 h2b = __float2bfloat16_rn(a2), h3b = __float2bfloat16_rn(a3);
    __nv_bfloat162 ahi01 = __halves2bfloat162(h0b, h1b);
    __nv_bfloat162 ahi23 = __halves2bfloat162(h2b, h3b);
    __nv_bfloat162 alo01 = __halves2bfloat162(
        __float2bfloat16_rn(a0 - __bfloat162float(h0b)),
        __float2bfloat16_rn(a1 - __bfloat162float(h1b)));
    __nv_bfloat162 alo23 = __halves2bfloat162(
        __float2bfloat16_rn(a2 - __bfloat162float(h2b)),
        __float2bfloat16_rn(a3 - __bfloat162float(h3b)));
    const __nv_bfloat162 z2 = __float2bfloat162_rn(0.f);
    int half = q >> 2, tt = q & 3;

    if (blockIdx.z < 8) {
        // ------- vertical (dirs 0, 2), 32-row chunk, warm 16 -------
        int cn = blockIdx.z;
        int w = threadIdx.x;
        const uint2* xp = bufA2 + ((size_t)(b * 8 + q)) * HW + w;
        const uint32_t* wm0 = wmapb + ((size_t)b * 4 + 0) * HW + w;
        const uint32_t* wm2 = wmapb + ((size_t)b * 4 + 2) * HW + w;
        uint2* g0 = gated2 + ((size_t)((b * 8 + 0 + half) * 4 + tt)) * HW + w;
        uint2* g2 = gated2 + ((size_t)((b * 8 + 4 + half) * 4 + tt)) * HW + w;
        int h0 = cn * 32;

        __nv_bfloat162 p01 = z2, p23 = z2;
#pragma unroll 4
        for (int h = max(0, h0 - 16); h < h0 + 32; h++) {
            size_t o = (size_t)h * WW;
            uint2 wv = xp[o];
            __nv_bfloat162 v01 = __hfma2(ahi01, p01, u2b(wv.x));
            v01 = __hfma2(alo01, p01, v01);
            v01 = __hmax2(v01, z2);
            __nv_bfloat162 v23 = __hfma2(ahi23, p23, u2b(wv.y));
            v23 = __hfma2(alo23, p23, v23);
            v23 = __hmax2(v23, z2);
            if (h >= h0) {
                __nv_bfloat162 m2 = u2b(wm0[o]);
                g0[o] = make_uint2(b2u(__hmul2(v01, m2)), b2u(__hmul2(v23, m2)));
            }
            p01 = v01; p23 = v23;
        }
        p01 = z2; p23 = z2;
#pragma unroll 4
        for (int h = min(HH - 1, h0 + 31 + 16); h >= h0; h--) {
            size_t o = (size_t)h * WW;
            uint2 wv = xp[o];
            __nv_bfloat162 v01 = __hfma2(ahi01, p01, u2b(wv.x));
            v01 = __hfma2(alo01, p01, v01);
            v01 = __hmax2(v01, z2);
            __nv_bfloat162 v23 = __hfma2(ahi23, p23, u2b(wv.y));
            v23 = __hfma2(alo23, p23, v23);
            v23 = __hmax2(v23, z2);
            if (h < h0 + 32) {
                __nv_bfloat162 m2 = u2b(wm2[o]);
                g2[o] = make_uint2(b2u(__hmul2(v01, m2)), b2u(__hmul2(v23, m2)));
            }
            p01 = v01; p23 = v23;
        }
        return;
    }

    // ------- horizontal (dirs 1, 3), 8-row block, 16-col chunks, warm 16 -------
    extern __shared__ uint2 shu[];
    uint2* tin = shu;
    uint2* tf  = shu + 8 * HSTRIDE;
    uint2* tr  = shu + 16 * HSTRIDE;

    int rb = blockIdx.z - 8;
    int R0 = rb * 8;
    const int tid = threadIdx.x;

    const uint2* xp = bufA2 + ((size_t)(b * 8 + q)) * HW + (size_t)R0 * WW;
    for (int i = tid; i < 8 * 256; i += 256) {
        int r = i >> 8, col = i & 255;
        tin[r * HSTRIDE + col] = xp[(size_t)r * WW + col];
    }
    __syncthreads();

    {
        int dir = tid >> 7, rem = tid & 127;
        int r = rem & 7, ck = rem >> 3;
        int base = ck * 16;
        uint2* dst = dir ? tr : tf;
        __nv_bfloat162 p01 = z2, p23 = z2;
        if (!dir) {
            for (int col = max(0, base - 16); col < base + 16; col++) {
                uint2 wv = tin[r * HSTRIDE + col];
                __nv_bfloat162 v01 = __hfma2(ahi01, p01, u2b(wv.x));
                v01 = __hfma2(alo01, p01, v01);
                v01 = __hmax2(v01, z2);
                __nv_bfloat162 v23 = __hfma2(ahi23, p23, u2b(wv.y));
                v23 = __hfma2(alo23, p23, v23);
                v23 = __hmax2(v23, z2);
                if (col >= base)
                    dst[r * HSTRIDE + col] = make_uint2(b2u(v01), b2u(v23));
                p01 = v01; p23 = v23;
            }
        } else {
            for (int col = min(255, base + 31); col >= base; col--) {
                uint2 wv = tin[r * HSTRIDE + col];
                __nv_bfloat162 v01 = __hfma2(ahi01, p01, u2b(wv.x));
                v01 = __hfma2(alo01, p01, v01);
                v01 = __hmax2(v01, z2);
                __nv_bfloat162 v23 = __hfma2(ahi23, p23, u2b(wv.y));
                v23 = __hfma2(alo23, p23, v23);
                v23 = __hmax2(v23, z2);
                if (col < base + 16)
                    dst[r * HSTRIDE + col] = make_uint2(b2u(v01), b2u(v23));
                p01 = v01; p23 = v23;
            }
        }
    }
    __syncthreads();

    const uint32_t* wm1 = wmapb + ((size_t)b * 4 + 1) * HW + (size_t)R0 * WW;
    const uint32_t* wm3 = wmapb + ((size_t)b * 4 + 3) * HW + (size_t)R0 * WW;
    uint2* g1 = gated2 + ((size_t)((b * 8 + 2 + half) * 4 + tt)) * HW + (size_t)R0 * WW;
    uint2* g3 = gated2 + ((size_t)((b * 8 + 6 + half) * 4 + tt)) * HW + (size_t)R0 * WW;
    for (int i = tid; i < 8 * 256; i += 256) {
        int r = i >> 8, col = i & 255;
        __nv_bfloat162 m1 = u2b(wm1[i]);
        __nv_bfloat162 m3 = u2b(wm3[i]);
        uint2 f = tf[r * HSTRIDE + col];
        uint2 rv = tr[r * HSTRIDE + col];
        g1[i] = make_uint2(b2u(__hmul2(u2b(f.x), m1)), b2u(__hmul2(u2b(f.y), m1)));
        g3[i] = make_uint2(b2u(__hmul2(u2b(rv.x), m3)), b2u(__hmul2(u2b(rv.y), m3)));
    }
}

// ---------------- launch ------------------------------------------------------
extern "C" void kernel_launch(void* const* d_in, const int* in_sizes, int n_in,
                              void* d_out, int out_size) {
    const float* x      = (const float*)d_in[0];
    const float* alpha1 = (const float*)d_in[1];
    const float* alpha2 = (const float*)d_in[2];
    const float* w_in   = (const float*)d_in[3];
    const float* w2     = (const float*)d_in[4];
    const float* w3     = (const float*)d_in[5];
    const float* att_w1 = (const float*)d_in[6];
    const float* att_w2 = (const float*)d_in[7];
    const float* att_w3 = (const float*)d_in[8];
    const float* att_b3 = (const float*)d_in[9];
    const float* w_out  = (const float*)d_in[10];
    float* out = (float*)d_out;

    __nv_bfloat16 *att1;
    uint32_t *wmapb;
    uint2 *bufA2, *gated2, *x2;
    uint4* wp;
    cudaGetSymbolAddress((void**)&bufA2, g_bufA2);
    cudaGetSymbolAddress((void**)&gated2, g_gated2);
    cudaGetSymbolAddress((void**)&wmapb, g_wmapb);
    cudaGetSymbolAddress((void**)&x2, g_x2);
    cudaGetSymbolAddress((void**)&wp, g_wp);
    cudaGetSymbolAddress((void**)&att1, g_att1);

    constexpr int SMP32 = 3 * (2448 + 9 * 4 * 36) * 8 + 2448 * 4;   // 99648
    constexpr int SMH   = 24 * HSTRIDE * 8;                          // 50112
    cudaFuncSetAttribute(conv_stage1, cudaFuncAttributeMaxDynamicSharedMemorySize, SMP32);
    cudaFuncSetAttribute(conv_mid, cudaFuncAttributeMaxDynamicSharedMemorySize, SMP32);
    cudaFuncSetAttribute(conv_last, cudaFuncAttributeMaxDynamicSharedMemorySize, SMP32);
    cudaFuncSetAttribute(scan_both, cudaFuncAttributeMaxDynamicSharedMemorySize, SMH);

    dim3 blk(256);
    // 1) setup: repack x + prepack all weights
    setup_all<<<NXB + 100, blk>>>(x, x2, w_in, w2, w3, att_w1, att_w2, (uint2*)wp);

    // 2) conv1 (trunk) + att1 (attention), cp.async from packed x2
    conv_stage1<<<dim3(WW / 32, HH / 16, 2 * BB), blk, SMP32>>>(x2, wp, bufA2, att1);

    // 3) att2 + fused 1x1 + sigmoid -> wmapb (dup'd bf16)
    conv3x3_att2<<<dim3(WW / 32, HH / 16, BB), blk>>>(att1, wp + WP_AW2, att_w3, att_b3, wmapb);

    // 4) scans stage 1
    scan_both<<<dim3(BB, 8, 40), blk, SMH>>>(bufA2, alpha1, wmapb, gated2);

    // 5) conv2
    conv_mid<<<dim3(WW / 32, HH / 16, BB), blk, SMP32>>>(gated2, wp, bufA2);

    // 6) scans stage 2
    scan_both<<<dim3(BB, 8, 40), blk, SMH>>>(bufA2, alpha2, wmapb, gated2);

    // 7) conv3 + fused 1x1 + sigmoid -> mask
    conv_last<<<dim3(WW / 32, HH / 16, BB), blk, SMP32>>>(gated2, wp, out, w_out);
}